// round 1
// baseline (speedup 1.0000x reference)
#include <cuda_runtime.h>

#define FEAT 128
#define BM 128
#define BN 128
#define BK 16
#define PAD_BM 132   // pad to reduce transposed-store bank conflicts

// scratch for v @ Wvn  (N padded to 50176 rows)
__device__ float g_vWn[50176 * FEAT];

// ---------------------------------------------------------------------------
// Kernel 1: C = A[n,128] @ W[128,128].  blockIdx.y==0 -> Wvc, out=d_out (Zc)
//                                       blockIdx.y==1 -> Wvn, out=g_vWn
// 128x128 tile per CTA, 256 threads, 8x8 per-thread tile (split 4+4 fragments).
// ---------------------------------------------------------------------------
__global__ __launch_bounds__(256) void gemm_kernel(
    const float* __restrict__ A,
    const float* __restrict__ Wvc,
    const float* __restrict__ Wvn,
    float* __restrict__ outZc,
    int n)
{
    __shared__ float As[BK][PAD_BM];   // transposed A tile: As[k][m]
    __shared__ float Bs[BK][BN];       // W tile: Bs[k][ncol]

    const float* W = (blockIdx.y == 0) ? Wvc : Wvn;
    float* Out     = (blockIdx.y == 0) ? outZc : g_vWn;

    int tid = threadIdx.x;
    int tx = tid & 15;     // 0..15 -> column group
    int ty = tid >> 4;     // 0..15 -> row group
    int blockRow = blockIdx.x * BM;

    float acc[8][8];
    #pragma unroll
    for (int i = 0; i < 8; i++)
        #pragma unroll
        for (int j = 0; j < 8; j++)
            acc[i][j] = 0.0f;

    for (int k0 = 0; k0 < FEAT; k0 += BK) {
        // ---- load A tile (128 rows x 16 k) transposed into As ----
        #pragma unroll
        for (int i = 0; i < 2; i++) {
            int f4  = tid + i * 256;   // 0..511
            int row = f4 >> 2;         // 0..127
            int q   = f4 & 3;          // which float4 in the 16-wide k chunk
            int grow = blockRow + row;
            float4 v = make_float4(0.f, 0.f, 0.f, 0.f);
            if (grow < n)
                v = reinterpret_cast<const float4*>(A)[grow * (FEAT / 4) + (k0 >> 2) + q];
            As[4 * q + 0][row] = v.x;
            As[4 * q + 1][row] = v.y;
            As[4 * q + 2][row] = v.z;
            As[4 * q + 3][row] = v.w;
        }
        // ---- load W tile (16 k x 128 cols) ----
        #pragma unroll
        for (int i = 0; i < 2; i++) {
            int f4 = tid + i * 256;    // 0..511
            int kk = f4 >> 5;          // 0..15
            int c4 = f4 & 31;          // 0..31 float4 columns
            reinterpret_cast<float4*>(&Bs[kk][0])[c4] =
                reinterpret_cast<const float4*>(W)[(k0 + kk) * (FEAT / 4) + c4];
        }
        __syncthreads();

        // ---- compute ----
        #pragma unroll
        for (int kk = 0; kk < BK; kk++) {
            float4 a0 = *reinterpret_cast<const float4*>(&As[kk][ty * 4]);
            float4 a1 = *reinterpret_cast<const float4*>(&As[kk][64 + ty * 4]);
            float4 b0 = *reinterpret_cast<const float4*>(&Bs[kk][tx * 4]);
            float4 b1 = *reinterpret_cast<const float4*>(&Bs[kk][64 + tx * 4]);
            float a[8] = {a0.x, a0.y, a0.z, a0.w, a1.x, a1.y, a1.z, a1.w};
            float b[8] = {b0.x, b0.y, b0.z, b0.w, b1.x, b1.y, b1.z, b1.w};
            #pragma unroll
            for (int i = 0; i < 8; i++)
                #pragma unroll
                for (int j = 0; j < 8; j++)
                    acc[i][j] = fmaf(a[i], b[j], acc[i][j]);
        }
        __syncthreads();
    }

    // ---- store ----
    #pragma unroll
    for (int i = 0; i < 8; i++) {
        int r = (i < 4) ? (ty * 4 + i) : (64 + ty * 4 + (i - 4));
        int grow = blockRow + r;
        if (grow < n) {
            float4* o = reinterpret_cast<float4*>(Out + (size_t)grow * FEAT);
            o[tx]      = make_float4(acc[i][0], acc[i][1], acc[i][2], acc[i][3]);
            o[16 + tx] = make_float4(acc[i][4], acc[i][5], acc[i][6], acc[i][7]);
        }
    }
}

// ---------------------------------------------------------------------------
// Kernel 2: per-row neighbor gather + epilogue.
// One warp per row; lane owns float4 columns [lane*4, lane*4+4).
// out[i] = relu(Zc[i] + (sum_j valid e_j * vWn[idx_j]) / cnt + bv)
// ---------------------------------------------------------------------------
__global__ __launch_bounds__(256) void gather_kernel(
    float* __restrict__ out,
    const int* __restrict__ nh_idx,
    const int* __restrict__ int_idx,
    const float* __restrict__ nh_e,
    const float* __restrict__ int_e,
    const float* __restrict__ bv,
    int n)
{
    int gwarp = (blockIdx.x * blockDim.x + threadIdx.x) >> 5;
    int lane  = threadIdx.x & 31;
    if (gwarp >= n) return;
    int row = gwarp;

    const float4* vW4 = reinterpret_cast<const float4*>(g_vWn);

    float4 acc = make_float4(0.f, 0.f, 0.f, 0.f);
    int cnt = 0;

    #pragma unroll
    for (int j = 0; j < 20; j++) {
        int   idx = __ldg(nh_idx + row * 20 + j);  // broadcast across warp
        float e   = __ldg(nh_e   + row * 20 + j);
        if (idx >= 0) {
            cnt++;
            float4 v = vW4[(size_t)idx * 32 + lane];
            acc.x = fmaf(e, v.x, acc.x);
            acc.y = fmaf(e, v.y, acc.y);
            acc.z = fmaf(e, v.z, acc.z);
            acc.w = fmaf(e, v.w, acc.w);
        }
    }
    #pragma unroll
    for (int j = 0; j < 20; j++) {
        int   idx = __ldg(int_idx + row * 20 + j);
        float e   = __ldg(int_e   + row * 20 + j);
        if (idx >= 0) {
            cnt++;
            float4 v = vW4[(size_t)idx * 32 + lane];
            acc.x = fmaf(e, v.x, acc.x);
            acc.y = fmaf(e, v.y, acc.y);
            acc.z = fmaf(e, v.z, acc.z);
            acc.w = fmaf(e, v.w, acc.w);
        }
    }

    float inv = 1.0f / (float)cnt;
    float4 zc = reinterpret_cast<const float4*>(out)[(size_t)row * 32 + lane];
    float4 b  = reinterpret_cast<const float4*>(bv)[lane];
    float4 z;
    z.x = fmaxf(fmaf(acc.x, inv, zc.x) + b.x, 0.f);
    z.y = fmaxf(fmaf(acc.y, inv, zc.y) + b.y, 0.f);
    z.z = fmaxf(fmaf(acc.z, inv, zc.z) + b.z, 0.f);
    z.w = fmaxf(fmaf(acc.w, inv, zc.w) + b.w, 0.f);
    reinterpret_cast<float4*>(out)[(size_t)row * 32 + lane] = z;
}

// ---------------------------------------------------------------------------
extern "C" void kernel_launch(void* const* d_in, const int* in_sizes, int n_in,
                              void* d_out, int out_size) {
    const float* vertices    = (const float*)d_in[0];
    const int*   nh_indices  = (const int*)  d_in[1];
    const int*   int_indices = (const int*)  d_in[2];
    const float* nh_edges    = (const float*)d_in[3];
    const float* int_edges   = (const float*)d_in[4];
    const float* Wvc         = (const float*)d_in[5];
    const float* Wvn         = (const float*)d_in[6];
    const float* bv          = (const float*)d_in[7];
    float* out = (float*)d_out;

    int n = in_sizes[0] / FEAT;   // 50000

    dim3 g1((n + BM - 1) / BM, 2);
    gemm_kernel<<<g1, 256>>>(vertices, Wvc, Wvn, out, n);

    int warps_per_block = 256 / 32;
    int g2 = (n + warps_per_block - 1) / warps_per_block;
    gather_kernel<<<g2, 256>>>(out, nh_indices, int_indices, nh_edges, int_edges, bv, n);
}

// round 2
// speedup vs baseline: 1.3597x; 1.3597x over previous
#include <cuda_runtime.h>

#define FEAT 128
#define BM 128
#define BN 128
#define BK 16
#define PAD_BM 132   // pad to reduce transposed-store bank conflicts

// scratch for v @ Wvn  (N padded to 50176 rows)
__device__ float g_vWn[50176 * FEAT];

// ---------------------------------------------------------------------------
// Kernel 1: C = A[n,128] @ W[128,128].  blockIdx.y==0 -> Wvc, out=d_out (Zc)
//                                       blockIdx.y==1 -> Wvn, out=g_vWn
// 128x128 tile per CTA, 256 threads, 8x8 per-thread tile (split 4+4 fragments).
// ---------------------------------------------------------------------------
__global__ __launch_bounds__(256) void gemm_kernel(
    const float* __restrict__ A,
    const float* __restrict__ Wvc,
    const float* __restrict__ Wvn,
    float* __restrict__ outZc,
    int n)
{
    __shared__ float As[BK][PAD_BM];   // transposed A tile: As[k][m]
    __shared__ float Bs[BK][BN];       // W tile: Bs[k][ncol]

    const float* W = (blockIdx.y == 0) ? Wvc : Wvn;
    float* Out     = (blockIdx.y == 0) ? outZc : g_vWn;

    int tid = threadIdx.x;
    int tx = tid & 15;     // 0..15 -> column group
    int ty = tid >> 4;     // 0..15 -> row group
    int blockRow = blockIdx.x * BM;

    float acc[8][8];
    #pragma unroll
    for (int i = 0; i < 8; i++)
        #pragma unroll
        for (int j = 0; j < 8; j++)
            acc[i][j] = 0.0f;

    for (int k0 = 0; k0 < FEAT; k0 += BK) {
        // ---- load A tile (128 rows x 16 k) transposed into As ----
        #pragma unroll
        for (int i = 0; i < 2; i++) {
            int f4  = tid + i * 256;   // 0..511
            int row = f4 >> 2;         // 0..127
            int q   = f4 & 3;          // which float4 in the 16-wide k chunk
            int grow = blockRow + row;
            float4 v = make_float4(0.f, 0.f, 0.f, 0.f);
            if (grow < n)
                v = reinterpret_cast<const float4*>(A)[grow * (FEAT / 4) + (k0 >> 2) + q];
            As[4 * q + 0][row] = v.x;
            As[4 * q + 1][row] = v.y;
            As[4 * q + 2][row] = v.z;
            As[4 * q + 3][row] = v.w;
        }
        // ---- load W tile (16 k x 128 cols) ----
        #pragma unroll
        for (int i = 0; i < 2; i++) {
            int f4 = tid + i * 256;    // 0..511
            int kk = f4 >> 5;          // 0..15
            int c4 = f4 & 31;          // 0..31 float4 columns
            reinterpret_cast<float4*>(&Bs[kk][0])[c4] =
                reinterpret_cast<const float4*>(W)[(k0 + kk) * (FEAT / 4) + c4];
        }
        __syncthreads();

        // ---- compute ----
        #pragma unroll
        for (int kk = 0; kk < BK; kk++) {
            float4 a0 = *reinterpret_cast<const float4*>(&As[kk][ty * 4]);
            float4 a1 = *reinterpret_cast<const float4*>(&As[kk][64 + ty * 4]);
            float4 b0 = *reinterpret_cast<const float4*>(&Bs[kk][tx * 4]);
            float4 b1 = *reinterpret_cast<const float4*>(&Bs[kk][64 + tx * 4]);
            float a[8] = {a0.x, a0.y, a0.z, a0.w, a1.x, a1.y, a1.z, a1.w};
            float b[8] = {b0.x, b0.y, b0.z, b0.w, b1.x, b1.y, b1.z, b1.w};
            #pragma unroll
            for (int i = 0; i < 8; i++)
                #pragma unroll
                for (int j = 0; j < 8; j++)
                    acc[i][j] = fmaf(a[i], b[j], acc[i][j]);
        }
        __syncthreads();
    }

    // ---- store ----
    #pragma unroll
    for (int i = 0; i < 8; i++) {
        int r = (i < 4) ? (ty * 4 + i) : (64 + ty * 4 + (i - 4));
        int grow = blockRow + r;
        if (grow < n) {
            float4* o = reinterpret_cast<float4*>(Out + (size_t)grow * FEAT);
            o[tx]      = make_float4(acc[i][0], acc[i][1], acc[i][2], acc[i][3]);
            o[16 + tx] = make_float4(acc[i][4], acc[i][5], acc[i][6], acc[i][7]);
        }
    }
}

// ---------------------------------------------------------------------------
// Kernel 2: per-row neighbor gather + epilogue (BRANCHLESS).
// One warp per row; lane owns float4 columns [lane*4, lane*4+4).
// out[i] = relu(Zc[i] + (sum_j valid e_j * vWn[idx_j]) / cnt + bv)
//
// All 40 gathers are unconditional (invalid -> idx 0, edge 0) so ptxas can
// front-batch independent LDG.128s and hide L2 latency.
// ---------------------------------------------------------------------------
__global__ __launch_bounds__(256, 4) void gather_kernel(
    float* __restrict__ out,
    const int* __restrict__ nh_idx,
    const int* __restrict__ int_idx,
    const float* __restrict__ nh_e,
    const float* __restrict__ int_e,
    const float* __restrict__ bv,
    int n)
{
    int gwarp = (blockIdx.x * blockDim.x + threadIdx.x) >> 5;
    int lane  = threadIdx.x & 31;
    if (gwarp >= n) return;
    int row = gwarp;

    const float4* vW4 = reinterpret_cast<const float4*>(g_vWn);

    // ---- load all indices + edges, vectorized (broadcast within warp) ----
    int   idxs[40];
    float es[40];
    {
        const int4*   ni4 = reinterpret_cast<const int4*>(nh_idx  + row * 20);
        const int4*   ii4 = reinterpret_cast<const int4*>(int_idx + row * 20);
        const float4* ne4 = reinterpret_cast<const float4*>(nh_e  + row * 20);
        const float4* ie4 = reinterpret_cast<const float4*>(int_e + row * 20);
        #pragma unroll
        for (int q = 0; q < 5; q++) {
            int4   a = __ldg(ni4 + q);
            float4 e = __ldg(ne4 + q);
            idxs[4*q+0] = a.x; idxs[4*q+1] = a.y; idxs[4*q+2] = a.z; idxs[4*q+3] = a.w;
            es[4*q+0] = e.x; es[4*q+1] = e.y; es[4*q+2] = e.z; es[4*q+3] = e.w;
        }
        #pragma unroll
        for (int q = 0; q < 5; q++) {
            int4   a = __ldg(ii4 + q);
            float4 e = __ldg(ie4 + q);
            idxs[20+4*q+0] = a.x; idxs[20+4*q+1] = a.y; idxs[20+4*q+2] = a.z; idxs[20+4*q+3] = a.w;
            es[20+4*q+0] = e.x; es[20+4*q+1] = e.y; es[20+4*q+2] = e.z; es[20+4*q+3] = e.w;
        }
    }

    // ---- branchless validity: count + zero edges + clamp indices ----
    int cnt = 0;
    #pragma unroll
    for (int j = 0; j < 40; j++) {
        bool v = idxs[j] >= 0;
        cnt += v ? 1 : 0;
        es[j]   = v ? es[j] : 0.0f;
        idxs[j] = v ? idxs[j] : 0;
    }

    // ---- unconditional gathers, two accumulator chains for ILP ----
    float4 acc0 = make_float4(0.f, 0.f, 0.f, 0.f);
    float4 acc1 = make_float4(0.f, 0.f, 0.f, 0.f);
    #pragma unroll
    for (int j = 0; j < 40; j += 2) {
        float4 v0 = __ldg(vW4 + (size_t)idxs[j]   * 32 + lane);
        float4 v1 = __ldg(vW4 + (size_t)idxs[j+1] * 32 + lane);
        float  e0 = es[j], e1 = es[j+1];
        acc0.x = fmaf(e0, v0.x, acc0.x);
        acc0.y = fmaf(e0, v0.y, acc0.y);
        acc0.z = fmaf(e0, v0.z, acc0.z);
        acc0.w = fmaf(e0, v0.w, acc0.w);
        acc1.x = fmaf(e1, v1.x, acc1.x);
        acc1.y = fmaf(e1, v1.y, acc1.y);
        acc1.z = fmaf(e1, v1.z, acc1.z);
        acc1.w = fmaf(e1, v1.w, acc1.w);
    }
    float4 acc = make_float4(acc0.x + acc1.x, acc0.y + acc1.y,
                             acc0.z + acc1.z, acc0.w + acc1.w);

    float inv = 1.0f / (float)cnt;
    float4 zc = reinterpret_cast<const float4*>(out)[(size_t)row * 32 + lane];
    float4 b  = __ldg(reinterpret_cast<const float4*>(bv) + lane);
    float4 z;
    z.x = fmaxf(fmaf(acc.x, inv, zc.x) + b.x, 0.f);
    z.y = fmaxf(fmaf(acc.y, inv, zc.y) + b.y, 0.f);
    z.z = fmaxf(fmaf(acc.z, inv, zc.z) + b.z, 0.f);
    z.w = fmaxf(fmaf(acc.w, inv, zc.w) + b.w, 0.f);
    reinterpret_cast<float4*>(out)[(size_t)row * 32 + lane] = z;
}

// ---------------------------------------------------------------------------
extern "C" void kernel_launch(void* const* d_in, const int* in_sizes, int n_in,
                              void* d_out, int out_size) {
    const float* vertices    = (const float*)d_in[0];
    const int*   nh_indices  = (const int*)  d_in[1];
    const int*   int_indices = (const int*)  d_in[2];
    const float* nh_edges    = (const float*)d_in[3];
    const float* int_edges   = (const float*)d_in[4];
    const float* Wvc         = (const float*)d_in[5];
    const float* Wvn         = (const float*)d_in[6];
    const float* bv          = (const float*)d_in[7];
    float* out = (float*)d_out;

    int n = in_sizes[0] / FEAT;   // 50000

    dim3 g1((n + BM - 1) / BM, 2);
    gemm_kernel<<<g1, 256>>>(vertices, Wvc, Wvn, out, n);

    int warps_per_block = 256 / 32;
    int g2 = (n + warps_per_block - 1) / warps_per_block;
    gather_kernel<<<g2, 256>>>(out, nh_indices, int_indices, nh_edges, int_edges, bv, n);
}

// round 3
// speedup vs baseline: 1.5498x; 1.1398x over previous
#include <cuda_runtime.h>
#include <cuda_fp16.h>

#define FEAT 128
#define BM 128
#define BN 128
#define BK 16
#define PAD_BM 132   // pad to reduce transposed-store bank conflicts

// scratch for v @ Wvn in fp16  (N padded to 50176 rows)
__device__ __half g_vWn_h[50176 * FEAT];

// ---------------------------------------------------------------------------
// Kernel 1: C = A[n,128] @ W[128,128].  blockIdx.y==0 -> Wvc, out=d_out (fp32)
//                                       blockIdx.y==1 -> Wvn, out=g_vWn_h (fp16)
// 128x128 tile per CTA, 256 threads, 8x8 per-thread tile (split 4+4 fragments).
// ---------------------------------------------------------------------------
__global__ __launch_bounds__(256) void gemm_kernel(
    const float* __restrict__ A,
    const float* __restrict__ Wvc,
    const float* __restrict__ Wvn,
    float* __restrict__ outZc,
    int n)
{
    __shared__ float As[BK][PAD_BM];   // transposed A tile: As[k][m]
    __shared__ float Bs[BK][BN];       // W tile: Bs[k][ncol]

    const bool isZc = (blockIdx.y == 0);
    const float* W = isZc ? Wvc : Wvn;

    int tid = threadIdx.x;
    int tx = tid & 15;     // 0..15 -> column group
    int ty = tid >> 4;     // 0..15 -> row group
    int blockRow = blockIdx.x * BM;

    float acc[8][8];
    #pragma unroll
    for (int i = 0; i < 8; i++)
        #pragma unroll
        for (int j = 0; j < 8; j++)
            acc[i][j] = 0.0f;

    for (int k0 = 0; k0 < FEAT; k0 += BK) {
        // ---- load A tile (128 rows x 16 k) transposed into As ----
        #pragma unroll
        for (int i = 0; i < 2; i++) {
            int f4  = tid + i * 256;   // 0..511
            int row = f4 >> 2;         // 0..127
            int q   = f4 & 3;          // which float4 in the 16-wide k chunk
            int grow = blockRow + row;
            float4 v = make_float4(0.f, 0.f, 0.f, 0.f);
            if (grow < n)
                v = reinterpret_cast<const float4*>(A)[grow * (FEAT / 4) + (k0 >> 2) + q];
            As[4 * q + 0][row] = v.x;
            As[4 * q + 1][row] = v.y;
            As[4 * q + 2][row] = v.z;
            As[4 * q + 3][row] = v.w;
        }
        // ---- load W tile (16 k x 128 cols) ----
        #pragma unroll
        for (int i = 0; i < 2; i++) {
            int f4 = tid + i * 256;    // 0..511
            int kk = f4 >> 5;          // 0..15
            int c4 = f4 & 31;          // 0..31 float4 columns
            reinterpret_cast<float4*>(&Bs[kk][0])[c4] =
                reinterpret_cast<const float4*>(W)[(k0 + kk) * (FEAT / 4) + c4];
        }
        __syncthreads();

        // ---- compute ----
        #pragma unroll
        for (int kk = 0; kk < BK; kk++) {
            float4 a0 = *reinterpret_cast<const float4*>(&As[kk][ty * 4]);
            float4 a1 = *reinterpret_cast<const float4*>(&As[kk][64 + ty * 4]);
            float4 b0 = *reinterpret_cast<const float4*>(&Bs[kk][tx * 4]);
            float4 b1 = *reinterpret_cast<const float4*>(&Bs[kk][64 + tx * 4]);
            float a[8] = {a0.x, a0.y, a0.z, a0.w, a1.x, a1.y, a1.z, a1.w};
            float b[8] = {b0.x, b0.y, b0.z, b0.w, b1.x, b1.y, b1.z, b1.w};
            #pragma unroll
            for (int i = 0; i < 8; i++)
                #pragma unroll
                for (int j = 0; j < 8; j++)
                    acc[i][j] = fmaf(a[i], b[j], acc[i][j]);
        }
        __syncthreads();
    }

    // ---- store ----
    if (isZc) {
        #pragma unroll
        for (int i = 0; i < 8; i++) {
            int r = (i < 4) ? (ty * 4 + i) : (64 + ty * 4 + (i - 4));
            int grow = blockRow + r;
            if (grow < n) {
                float4* o = reinterpret_cast<float4*>(outZc + (size_t)grow * FEAT);
                o[tx]      = make_float4(acc[i][0], acc[i][1], acc[i][2], acc[i][3]);
                o[16 + tx] = make_float4(acc[i][4], acc[i][5], acc[i][6], acc[i][7]);
            }
        }
    } else {
        // fp16 output for the gather stage
        #pragma unroll
        for (int i = 0; i < 8; i++) {
            int r = (i < 4) ? (ty * 4 + i) : (64 + ty * 4 + (i - 4));
            int grow = blockRow + r;
            if (grow < n) {
                __half2* o = reinterpret_cast<__half2*>(g_vWn_h + (size_t)grow * FEAT);
                o[tx * 2 + 0]      = __floats2half2_rn(acc[i][0], acc[i][1]);
                o[tx * 2 + 1]      = __floats2half2_rn(acc[i][2], acc[i][3]);
                o[32 + tx * 2 + 0] = __floats2half2_rn(acc[i][4], acc[i][5]);
                o[32 + tx * 2 + 1] = __floats2half2_rn(acc[i][6], acc[i][7]);
            }
        }
    }
}

// ---------------------------------------------------------------------------
// Kernel 2: per-row neighbor gather + epilogue (BRANCHLESS, fp16 gathers).
// One warp per row; lane owns columns [lane*4, lane*4+4) = one uint2 (4 halves).
// out[i] = relu(Zc[i] + (sum_j valid e_j * vWn[idx_j]) / cnt + bv)
// ---------------------------------------------------------------------------
__global__ __launch_bounds__(256, 4) void gather_kernel(
    float* __restrict__ out,
    const int* __restrict__ nh_idx,
    const int* __restrict__ int_idx,
    const float* __restrict__ nh_e,
    const float* __restrict__ int_e,
    const float* __restrict__ bv,
    int n)
{
    int gwarp = (blockIdx.x * blockDim.x + threadIdx.x) >> 5;
    int lane  = threadIdx.x & 31;
    if (gwarp >= n) return;
    int row = gwarp;

    const uint2* vW2 = reinterpret_cast<const uint2*>(g_vWn_h);  // 8B = 4 halves; 32 per row

    // ---- load all indices + edges, vectorized (broadcast within warp) ----
    int   idxs[40];
    float es[40];
    {
        const int4*   ni4 = reinterpret_cast<const int4*>(nh_idx  + row * 20);
        const int4*   ii4 = reinterpret_cast<const int4*>(int_idx + row * 20);
        const float4* ne4 = reinterpret_cast<const float4*>(nh_e  + row * 20);
        const float4* ie4 = reinterpret_cast<const float4*>(int_e + row * 20);
        #pragma unroll
        for (int q = 0; q < 5; q++) {
            int4   a = __ldg(ni4 + q);
            float4 e = __ldg(ne4 + q);
            idxs[4*q+0] = a.x; idxs[4*q+1] = a.y; idxs[4*q+2] = a.z; idxs[4*q+3] = a.w;
            es[4*q+0] = e.x; es[4*q+1] = e.y; es[4*q+2] = e.z; es[4*q+3] = e.w;
        }
        #pragma unroll
        for (int q = 0; q < 5; q++) {
            int4   a = __ldg(ii4 + q);
            float4 e = __ldg(ie4 + q);
            idxs[20+4*q+0] = a.x; idxs[20+4*q+1] = a.y; idxs[20+4*q+2] = a.z; idxs[20+4*q+3] = a.w;
            es[20+4*q+0] = e.x; es[20+4*q+1] = e.y; es[20+4*q+2] = e.z; es[20+4*q+3] = e.w;
        }
    }

    // ---- branchless validity: count + zero edges + clamp indices ----
    int cnt = 0;
    #pragma unroll
    for (int j = 0; j < 40; j++) {
        bool v = idxs[j] >= 0;
        cnt += v ? 1 : 0;
        es[j]   = v ? es[j] : 0.0f;
        idxs[j] = v ? idxs[j] : 0;
    }

    // ---- unconditional fp16 gathers, two accumulator chains for ILP ----
    float4 acc0 = make_float4(0.f, 0.f, 0.f, 0.f);
    float4 acc1 = make_float4(0.f, 0.f, 0.f, 0.f);
    #pragma unroll
    for (int j = 0; j < 40; j += 2) {
        uint2 r0 = __ldg(vW2 + (size_t)idxs[j]   * 32 + lane);
        uint2 r1 = __ldg(vW2 + (size_t)idxs[j+1] * 32 + lane);
        float  e0 = es[j], e1 = es[j+1];
        float2 v0a = __half22float2(*reinterpret_cast<__half2*>(&r0.x));
        float2 v0b = __half22float2(*reinterpret_cast<__half2*>(&r0.y));
        float2 v1a = __half22float2(*reinterpret_cast<__half2*>(&r1.x));
        float2 v1b = __half22float2(*reinterpret_cast<__half2*>(&r1.y));
        acc0.x = fmaf(e0, v0a.x, acc0.x);
        acc0.y = fmaf(e0, v0a.y, acc0.y);
        acc0.z = fmaf(e0, v0b.x, acc0.z);
        acc0.w = fmaf(e0, v0b.y, acc0.w);
        acc1.x = fmaf(e1, v1a.x, acc1.x);
        acc1.y = fmaf(e1, v1a.y, acc1.y);
        acc1.z = fmaf(e1, v1b.x, acc1.z);
        acc1.w = fmaf(e1, v1b.y, acc1.w);
    }
    float4 acc = make_float4(acc0.x + acc1.x, acc0.y + acc1.y,
                             acc0.z + acc1.z, acc0.w + acc1.w);

    float inv = 1.0f / (float)cnt;
    float4 zc = reinterpret_cast<const float4*>(out)[(size_t)row * 32 + lane];
    float4 b  = __ldg(reinterpret_cast<const float4*>(bv) + lane);
    float4 z;
    z.x = fmaxf(fmaf(acc.x, inv, zc.x) + b.x, 0.f);
    z.y = fmaxf(fmaf(acc.y, inv, zc.y) + b.y, 0.f);
    z.z = fmaxf(fmaf(acc.z, inv, zc.z) + b.z, 0.f);
    z.w = fmaxf(fmaf(acc.w, inv, zc.w) + b.w, 0.f);
    reinterpret_cast<float4*>(out)[(size_t)row * 32 + lane] = z;
}

// ---------------------------------------------------------------------------
extern "C" void kernel_launch(void* const* d_in, const int* in_sizes, int n_in,
                              void* d_out, int out_size) {
    const float* vertices    = (const float*)d_in[0];
    const int*   nh_indices  = (const int*)  d_in[1];
    const int*   int_indices = (const int*)  d_in[2];
    const float* nh_edges    = (const float*)d_in[3];
    const float* int_edges   = (const float*)d_in[4];
    const float* Wvc         = (const float*)d_in[5];
    const float* Wvn         = (const float*)d_in[6];
    const float* bv          = (const float*)d_in[7];
    float* out = (float*)d_out;

    int n = in_sizes[0] / FEAT;   // 50000

    dim3 g1((n + BM - 1) / BM, 2);
    gemm_kernel<<<g1, 256>>>(vertices, Wvc, Wvn, out, n);

    int warps_per_block = 256 / 32;
    int g2 = (n + warps_per_block - 1) / warps_per_block;
    gather_kernel<<<g2, 256>>>(out, nh_indices, int_indices, nh_edges, int_edges, bv, n);
}

// round 5
// speedup vs baseline: 1.6456x; 1.0618x over previous
#include <cuda_runtime.h>
#include <cuda_fp16.h>
#include <cstdint>

#define FEAT 128
#define BM 128
#define BN 128
#define BK 16
#define PAD_BM 132   // pad to reduce transposed-store bank conflicts

// scratch for v @ Wvn in fp16  (N padded to 50176 rows)
__device__ __half g_vWn_h[50176 * FEAT];

// ---------------------------------------------------------------------------
// Packed dual-fp32 FMA (Blackwell family-wide, SASS FFMA2). Two independent
// fp32 FMAs per issue slot, identical rounding to fmaf.
// ---------------------------------------------------------------------------
__device__ __forceinline__ unsigned long long pack2(float x, float y) {
    unsigned long long r;
    asm("mov.b64 %0, {%1, %2};" : "=l"(r) : "f"(x), "f"(y));
    return r;
}
__device__ __forceinline__ float2 unpack2(unsigned long long v) {
    float2 f;
    asm("mov.b64 {%0, %1}, %2;" : "=f"(f.x), "=f"(f.y) : "l"(v));
    return f;
}
__device__ __forceinline__ void ffma2(unsigned long long& acc,
                                      unsigned long long a,
                                      unsigned long long b) {
    asm("fma.rn.f32x2 %0, %1, %2, %0;" : "+l"(acc) : "l"(a), "l"(b));
}

// ---------------------------------------------------------------------------
// Kernel 1: C = A[n,128] @ W[128,128].  blockIdx.y==0 -> Wvc, out=d_out (fp32)
//                                       blockIdx.y==1 -> Wvn, out=g_vWn_h (fp16)
// 128x128 tile per CTA, 256 threads, 8x8 per-thread tile computed with FFMA2.
// ---------------------------------------------------------------------------
__global__ __launch_bounds__(256) void gemm_kernel(
    const float* __restrict__ A,
    const float* __restrict__ Wvc,
    const float* __restrict__ Wvn,
    float* __restrict__ outZc,
    int n)
{
    __shared__ float As[BK][PAD_BM];   // transposed A tile: As[k][m]
    __shared__ float Bs[BK][BN];       // W tile: Bs[k][ncol]

    const bool isZc = (blockIdx.y == 0);
    const float* W = isZc ? Wvc : Wvn;

    int tid = threadIdx.x;
    int tx = tid & 15;     // 0..15 -> column group
    int ty = tid >> 4;     // 0..15 -> row group
    int blockRow = blockIdx.x * BM;

    // 8 rows x 8 cols accumulators as 8x4 packed fp32 pairs
    unsigned long long acc2[8][4];
    #pragma unroll
    for (int i = 0; i < 8; i++)
        #pragma unroll
        for (int j = 0; j < 4; j++)
            acc2[i][j] = 0ull;

    for (int k0 = 0; k0 < FEAT; k0 += BK) {
        // ---- load A tile (128 rows x 16 k) transposed into As ----
        #pragma unroll
        for (int i = 0; i < 2; i++) {
            int f4  = tid + i * 256;   // 0..511
            int row = f4 >> 2;         // 0..127
            int q   = f4 & 3;          // which float4 in the 16-wide k chunk
            int grow = blockRow + row;
            float4 v = make_float4(0.f, 0.f, 0.f, 0.f);
            if (grow < n)
                v = reinterpret_cast<const float4*>(A)[grow * (FEAT / 4) + (k0 >> 2) + q];
            As[4 * q + 0][row] = v.x;
            As[4 * q + 1][row] = v.y;
            As[4 * q + 2][row] = v.z;
            As[4 * q + 3][row] = v.w;
        }
        // ---- load W tile (16 k x 128 cols) ----
        #pragma unroll
        for (int i = 0; i < 2; i++) {
            int f4 = tid + i * 256;    // 0..511
            int kk = f4 >> 5;          // 0..15
            int c4 = f4 & 31;          // 0..31 float4 columns
            reinterpret_cast<float4*>(&Bs[kk][0])[c4] =
                reinterpret_cast<const float4*>(W)[(k0 + kk) * (FEAT / 4) + c4];
        }
        __syncthreads();

        // ---- compute (FFMA2) ----
        #pragma unroll
        for (int kk = 0; kk < BK; kk++) {
            float4 a0 = *reinterpret_cast<const float4*>(&As[kk][ty * 4]);
            float4 a1 = *reinterpret_cast<const float4*>(&As[kk][64 + ty * 4]);
            float4 b0 = *reinterpret_cast<const float4*>(&Bs[kk][tx * 4]);
            float4 b1 = *reinterpret_cast<const float4*>(&Bs[kk][64 + tx * 4]);

            unsigned long long bp[4] = {
                pack2(b0.x, b0.y), pack2(b0.z, b0.w),
                pack2(b1.x, b1.y), pack2(b1.z, b1.w)
            };
            float a[8] = {a0.x, a0.y, a0.z, a0.w, a1.x, a1.y, a1.z, a1.w};
            #pragma unroll
            for (int i = 0; i < 8; i++) {
                unsigned long long ap = pack2(a[i], a[i]);
                #pragma unroll
                for (int j = 0; j < 4; j++)
                    ffma2(acc2[i][j], ap, bp[j]);
            }
        }
        __syncthreads();
    }

    // ---- store ----
    if (isZc) {
        #pragma unroll
        for (int i = 0; i < 8; i++) {
            int r = (i < 4) ? (ty * 4 + i) : (64 + ty * 4 + (i - 4));
            int grow = blockRow + r;
            if (grow < n) {
                float2 p0 = unpack2(acc2[i][0]);
                float2 p1 = unpack2(acc2[i][1]);
                float2 p2 = unpack2(acc2[i][2]);
                float2 p3 = unpack2(acc2[i][3]);
                float4* o = reinterpret_cast<float4*>(outZc + (size_t)grow * FEAT);
                o[tx]      = make_float4(p0.x, p0.y, p1.x, p1.y);
                o[16 + tx] = make_float4(p2.x, p2.y, p3.x, p3.y);
            }
        }
    } else {
        // fp16 output for the gather stage
        #pragma unroll
        for (int i = 0; i < 8; i++) {
            int r = (i < 4) ? (ty * 4 + i) : (64 + ty * 4 + (i - 4));
            int grow = blockRow + r;
            if (grow < n) {
                float2 p0 = unpack2(acc2[i][0]);
                float2 p1 = unpack2(acc2[i][1]);
                float2 p2 = unpack2(acc2[i][2]);
                float2 p3 = unpack2(acc2[i][3]);
                __half2* o = reinterpret_cast<__half2*>(g_vWn_h + (size_t)grow * FEAT);
                o[tx * 2 + 0]      = __floats2half2_rn(p0.x, p0.y);
                o[tx * 2 + 1]      = __floats2half2_rn(p1.x, p1.y);
                o[32 + tx * 2 + 0] = __floats2half2_rn(p2.x, p2.y);
                o[32 + tx * 2 + 1] = __floats2half2_rn(p3.x, p3.y);
            }
        }
    }
}

// ---------------------------------------------------------------------------
// Kernel 2: per-row neighbor gather + epilogue (BRANCHLESS, fp16 gathers).
// One warp per row; lane owns columns [lane*4, lane*4+4) = one uint2 (4 halves).
// out[i] = relu(Zc[i] + (sum_j valid e_j * vWn[idx_j]) / cnt + bv)
// ---------------------------------------------------------------------------
__global__ __launch_bounds__(256, 4) void gather_kernel(
    float* __restrict__ out,
    const int* __restrict__ nh_idx,
    const int* __restrict__ int_idx,
    const float* __restrict__ nh_e,
    const float* __restrict__ int_e,
    const float* __restrict__ bv,
    int n)
{
    int gwarp = (blockIdx.x * blockDim.x + threadIdx.x) >> 5;
    int lane  = threadIdx.x & 31;
    if (gwarp >= n) return;
    int row = gwarp;

    const uint2* vW2 = reinterpret_cast<const uint2*>(g_vWn_h);

    int   idxs[40];
    float es[40];
    {
        const int4*   ni4 = reinterpret_cast<const int4*>(nh_idx  + row * 20);
        const int4*   ii4 = reinterpret_cast<const int4*>(int_idx + row * 20);
        const float4* ne4 = reinterpret_cast<const float4*>(nh_e  + row * 20);
        const float4* ie4 = reinterpret_cast<const float4*>(int_e + row * 20);
        #pragma unroll
        for (int q = 0; q < 5; q++) {
            int4   a = __ldg(ni4 + q);
            float4 e = __ldg(ne4 + q);
            idxs[4*q+0] = a.x; idxs[4*q+1] = a.y; idxs[4*q+2] = a.z; idxs[4*q+3] = a.w;
            es[4*q+0] = e.x; es[4*q+1] = e.y; es[4*q+2] = e.z; es[4*q+3] = e.w;
        }
        #pragma unroll
        for (int q = 0; q < 5; q++) {
            int4   a = __ldg(ii4 + q);
            float4 e = __ldg(ie4 + q);
            idxs[20+4*q+0] = a.x; idxs[20+4*q+1] = a.y; idxs[20+4*q+2] = a.z; idxs[20+4*q+3] = a.w;
            es[20+4*q+0] = e.x; es[20+4*q+1] = e.y; es[20+4*q+2] = e.z; es[20+4*q+3] = e.w;
        }
    }

    int cnt = 0;
    #pragma unroll
    for (int j = 0; j < 40; j++) {
        bool v = idxs[j] >= 0;
        cnt += v ? 1 : 0;
        es[j]   = v ? es[j] : 0.0f;
        idxs[j] = v ? idxs[j] : 0;
    }

    // unconditional fp16 gathers, packed f32x2 accumulate (two chains)
    unsigned long long accA0 = 0ull, accB0 = 0ull;  // chain 0: cols (0,1) and (2,3)
    unsigned long long accA1 = 0ull, accB1 = 0ull;  // chain 1
    #pragma unroll
    for (int j = 0; j < 40; j += 2) {
        uint2 r0 = __ldg(vW2 + (size_t)idxs[j]   * 32 + lane);
        uint2 r1 = __ldg(vW2 + (size_t)idxs[j+1] * 32 + lane);
        float2 v0a = __half22float2(*reinterpret_cast<__half2*>(&r0.x));
        float2 v0b = __half22float2(*reinterpret_cast<__half2*>(&r0.y));
        float2 v1a = __half22float2(*reinterpret_cast<__half2*>(&r1.x));
        float2 v1b = __half22float2(*reinterpret_cast<__half2*>(&r1.y));
        unsigned long long e0 = pack2(es[j],   es[j]);
        unsigned long long e1 = pack2(es[j+1], es[j+1]);
        ffma2(accA0, e0, pack2(v0a.x, v0a.y));
        ffma2(accB0, e0, pack2(v0b.x, v0b.y));
        ffma2(accA1, e1, pack2(v1a.x, v1a.y));
        ffma2(accB1, e1, pack2(v1b.x, v1b.y));
    }
    float2 a0 = unpack2(accA0), a1 = unpack2(accA1);
    float2 b0f = unpack2(accB0), b1f = unpack2(accB1);
    float4 acc = make_float4(a0.x + a1.x, a0.y + a1.y,
                             b0f.x + b1f.x, b0f.y + b1f.y);

    float inv = 1.0f / (float)cnt;
    float4 zc = reinterpret_cast<const float4*>(out)[(size_t)row * 32 + lane];
    float4 b  = __ldg(reinterpret_cast<const float4*>(bv) + lane);
    float4 z;
    z.x = fmaxf(fmaf(acc.x, inv, zc.x) + b.x, 0.f);
    z.y = fmaxf(fmaf(acc.y, inv, zc.y) + b.y, 0.f);
    z.z = fmaxf(fmaf(acc.z, inv, zc.z) + b.z, 0.f);
    z.w = fmaxf(fmaf(acc.w, inv, zc.w) + b.w, 0.f);
    reinterpret_cast<float4*>(out)[(size_t)row * 32 + lane] = z;
}

// ---------------------------------------------------------------------------
extern "C" void kernel_launch(void* const* d_in, const int* in_sizes, int n_in,
                              void* d_out, int out_size) {
    const float* vertices    = (const float*)d_in[0];
    const int*   nh_indices  = (const int*)  d_in[1];
    const int*   int_indices = (const int*)  d_in[2];
    const float* nh_edges    = (const float*)d_in[3];
    const float* int_edges   = (const float*)d_in[4];
    const float* Wvc         = (const float*)d_in[5];
    const float* Wvn         = (const float*)d_in[6];
    const float* bv          = (const float*)d_in[7];
    float* out = (float*)d_out;

    int n = in_sizes[0] / FEAT;   // 50000

    dim3 g1((n + BM - 1) / BM, 2);
    gemm_kernel<<<g1, 256>>>(vertices, Wvc, Wvn, out, n);

    int warps_per_block = 256 / 32;
    int g2 = (n + warps_per_block - 1) / warps_per_block;
    gather_kernel<<<g2, 256>>>(out, nh_indices, int_indices, nh_edges, int_edges, bv, n);
}